// round 10
// baseline (speedup 1.0000x reference)
#include <cuda_runtime.h>
#include <math.h>
#include <stdint.h>

#define KCODES 512
#define DIM 64
#define NROWS 262144
#define ROWS_PER_CTA 128
#define NBLOCKS (NROWS / ROWS_PER_CTA)   // 2048
#define TPB 256
#define EPS 1e-3f

#define WCH 68                            // words per code in smem W plane
#define PLANE_WORDS (64 * WCH)            // 4352 (one 64-code chunk)

// Scratch (no device-side allocation allowed)
__device__ float  g_sw[KCODES];
__device__ int    g_counts[KCODES];
__device__ double g_partial[NBLOCKS];
__device__ float  g_whi[KCODES * DIM];    // tf32(w) values (rna-rounded)

__device__ __forceinline__ uint32_t smem_u32(const void* p) {
    uint32_t a;
    asm("{ .reg .u64 t; cvta.to.shared.u64 t, %1; cvt.u32.u64 %0, t; }" : "=r"(a) : "l"(p));
    return a;
}
__device__ __forceinline__ uint32_t to_tf32(float f) {
    uint32_t r;
    asm("cvt.rna.tf32.f32 %0, %1;" : "=r"(r) : "f"(f));
    return r;
}
__device__ __forceinline__ void mma1688(float* c,
                                        const uint32_t* a,
                                        uint32_t b0, uint32_t b1) {
    asm volatile("mma.sync.aligned.m16n8k8.row.col.f32.tf32.tf32.f32 "
                 "{%0,%1,%2,%3}, {%4,%5,%6,%7}, {%8,%9}, {%0,%1,%2,%3};"
                 : "+f"(c[0]), "+f"(c[1]), "+f"(c[2]), "+f"(c[3])
                 : "r"(a[0]), "r"(a[1]), "r"(a[2]), "r"(a[3]), "r"(b0), "r"(b1));
}
__device__ __forceinline__ void cpasync16(uint32_t saddr, const void* g) {
    asm volatile("cp.async.cg.shared.global [%0], [%1], 16;" :: "r"(saddr), "l"(g) : "memory");
}

// ---------------------------------------------------------------------------
// Kernel 1: exact code norms (R2 association) + tf32(W) + hist zero
// ---------------------------------------------------------------------------
__global__ void vq_prep(const float* __restrict__ W) {
    int k = blockIdx.x * 64 + threadIdx.x;   // 8 x 64
    const float4* w = (const float4*)(W + (size_t)k * DIM);
    float4* wh = (float4*)(g_whi + (size_t)k * DIM);
    float s = 0.0f;
    #pragma unroll
    for (int g = 0; g < 16; ++g) {
        float4 v = w[g];
        s += v.x * v.x; s += v.y * v.y; s += v.z * v.z; s += v.w * v.w;
        float4 h;
        h.x = __uint_as_float(to_tf32(v.x));
        h.y = __uint_as_float(to_tf32(v.y));
        h.z = __uint_as_float(to_tf32(v.z));
        h.w = __uint_as_float(to_tf32(v.w));
        wh[g] = h;
    }
    g_sw[k] = s;
    g_counts[k] = 0;
}

// ---------------------------------------------------------------------------
// Kernel 2: fused TF32 scoring + in-register argmin + warp-exact fallback
// Output: out[0]=loss | out[1..1+N*64)=q_st | out[1+N*64]=perp | idx (float)
// ---------------------------------------------------------------------------
extern "C" __global__ void __launch_bounds__(TPB)
vq_main(const float* __restrict__ X, const float* __restrict__ W,
        float* __restrict__ out) {
    __shared__ float  s_w[2 * PLANE_WORDS];   // double-buffered tf32 W chunks, 34816 B
    __shared__ float  s_sw[KCODES];
    __shared__ double s_red[TPB];
    __shared__ int    s_idx[ROWS_PER_CTA];
    __shared__ int    s_list[ROWS_PER_CTA];
    __shared__ int    s_cnt;

    const int tid  = threadIdx.x;
    const int lane = tid & 31;
    const int warp = tid >> 5;
    const int g    = lane >> 2;      // row group 0..7
    const int tl   = lane & 3;       // k-dim group 0..3
    const int rowBase = blockIdx.x * ROWS_PER_CTA;

    if (tid == 0) s_cnt = 0;
    for (int i = tid; i < KCODES; i += TPB) s_sw[i] = g_sw[i];

    const uint32_t swbase = smem_u32(s_w);

    // prefetch chunk 0 (64 codes x 64 tf32)
    {
        const float4* src = (const float4*)g_whi;
        #pragma unroll
        for (int i = tid; i < 1024; i += TPB) {
            int code = i >> 4, d4 = i & 15;
            cpasync16(swbase + (uint32_t)(code * WCH + d4 * 4) * 4, src + i);
        }
        asm volatile("cp.async.commit_group;" ::: "memory");
    }

    // A fragments: 16 rows x 64 dims per warp (tf32-rna), registers
    uint32_t ah[8][4];
    {
        const float* xr0 = X + (size_t)(rowBase + warp * 16 + g) * DIM;
        const float* xr8 = xr0 + 8 * DIM;
        #pragma unroll
        for (int s = 0; s < 8; ++s) {
            ah[s][0] = to_tf32(xr0[8 * s + tl]);
            ah[s][1] = to_tf32(xr8[8 * s + tl]);
            ah[s][2] = to_tf32(xr0[8 * s + tl + 4]);
            ah[s][3] = to_tf32(xr8[8 * s + tl + 4]);
        }
    }

    // per-thread running argmin state for rows g (A) and g+8 (B)
    float bestA = __int_as_float(0x7f800000), best2A = bestA;
    float bestB = bestA, best2B = bestA;
    int idxA = 0, idxB = 0;

#define UPD(bst, bst2, bix, r, k)                       \
    { if ((r) < (bst)) { (bst2) = (bst); (bst) = (r); (bix) = (k); } \
      else if ((r) < (bst2)) (bst2) = (r); }

    // ---- chunk loop: 8 chunks of 64 codes, double-buffered ----
    for (int c = 0; c < 8; ++c) {
        const int buf = c & 1;
        asm volatile("cp.async.wait_group 0;" ::: "memory");
        __syncthreads();
        if (c < 7) {
            const float4* src = (const float4*)(g_whi + (size_t)(c + 1) * 64 * DIM);
            uint32_t dstb = swbase + (uint32_t)((buf ^ 1) * PLANE_WORDS) * 4;
            #pragma unroll
            for (int i = tid; i < 1024; i += TPB) {
                int code = i >> 4, d4 = i & 15;
                cpasync16(dstb + (uint32_t)(code * WCH + d4 * 4) * 4, src + i);
            }
            asm volatile("cp.async.commit_group;" ::: "memory");
        }

        const float* wh = s_w + buf * PLANE_WORDS;

        for (int tp = 0; tp < 8; tp += 2) {       // two code-octets interleaved
            float c0[4] = {0.f, 0.f, 0.f, 0.f};
            float c1[4] = {0.f, 0.f, 0.f, 0.f};
            #pragma unroll
            for (int s = 0; s < 8; ++s) {
                const int wo0 = (tp * 8 + g) * WCH + 8 * s + tl;      // conflict-free
                const int wo1 = wo0 + 8 * WCH;
                uint32_t b00 = __float_as_uint(wh[wo0]);
                uint32_t b01 = __float_as_uint(wh[wo0 + 4]);
                uint32_t b10 = __float_as_uint(wh[wo1]);
                uint32_t b11 = __float_as_uint(wh[wo1 + 4]);
                mma1688(c0, ah[s], b00, b01);
                mma1688(c1, ah[s], b10, b11);
            }
            // epilogue: r = sw_k - 2*dot, ascending-k updates
            {
                const int k0 = c * 64 + tp * 8 + 2 * tl;
                float sw0 = s_sw[k0], sw1 = s_sw[k0 + 1];
                UPD(bestA, best2A, idxA, fmaf(c0[0], -2.0f, sw0), k0);
                UPD(bestA, best2A, idxA, fmaf(c0[1], -2.0f, sw1), k0 + 1);
                UPD(bestB, best2B, idxB, fmaf(c0[2], -2.0f, sw0), k0);
                UPD(bestB, best2B, idxB, fmaf(c0[3], -2.0f, sw1), k0 + 1);
            }
            {
                const int k0 = c * 64 + tp * 8 + 8 + 2 * tl;
                float sw0 = s_sw[k0], sw1 = s_sw[k0 + 1];
                UPD(bestA, best2A, idxA, fmaf(c1[0], -2.0f, sw0), k0);
                UPD(bestA, best2A, idxA, fmaf(c1[1], -2.0f, sw1), k0 + 1);
                UPD(bestB, best2B, idxB, fmaf(c1[2], -2.0f, sw0), k0);
                UPD(bestB, best2B, idxB, fmaf(c1[3], -2.0f, sw1), k0 + 1);
            }
        }
    }
#undef UPD

    // ---- merge across the 4 tl-threads (same row), two-min semantics ----
    #pragma unroll
    for (int off = 1; off <= 2; off <<= 1) {
        float ob, ob2; int oi;
        ob  = __shfl_xor_sync(0xffffffffu, bestA, off);
        oi  = __shfl_xor_sync(0xffffffffu, idxA, off);
        ob2 = __shfl_xor_sync(0xffffffffu, best2A, off);
        if (ob < bestA || (ob == bestA && oi < idxA)) {
            best2A = fminf(bestA, fminf(ob2, best2A)); bestA = ob; idxA = oi;
        } else {
            best2A = fminf(ob, fminf(ob2, best2A));
        }
        ob  = __shfl_xor_sync(0xffffffffu, bestB, off);
        oi  = __shfl_xor_sync(0xffffffffu, idxB, off);
        ob2 = __shfl_xor_sync(0xffffffffu, best2B, off);
        if (ob < bestB || (ob == bestB && oi < idxB)) {
            best2B = fminf(bestB, fminf(ob2, best2B)); bestB = ob; idxB = oi;
        } else {
            best2B = fminf(ob, fminf(ob2, best2B));
        }
    }

    if (tl == 0) {
        const int rA = warp * 16 + g, rB = rA + 8;
        s_idx[rA] = idxA;
        s_idx[rB] = idxB;
        if (best2A - bestA < EPS) { int p = atomicAdd(&s_cnt, 1); s_list[p] = rA; }
        if (best2B - bestB < EPS) { int p = atomicAdd(&s_cnt, 1); s_list[p] = rB; }
    }
    __syncthreads();

    // ---- ambiguous rows: warp-cooperative EXACT scan (R2 comparator) ----
    const int namb = s_cnt;
    for (int i = warp; i < namb; i += 8) {
        const int r = s_list[i];
        const int rowG = rowBase + r;
        float4 x[16];
        const float4* xp = (const float4*)(X + (size_t)rowG * DIM);
        #pragma unroll
        for (int gg = 0; gg < 16; ++gg) x[gg] = xp[gg];
        float sx = 0.0f;
        #pragma unroll
        for (int gg = 0; gg < 16; ++gg) {
            sx += x[gg].x * x[gg].x; sx += x[gg].y * x[gg].y;
            sx += x[gg].z * x[gg].z; sx += x[gg].w * x[gg].w;
        }
        float bd = __int_as_float(0x7f800000);
        int bi = KCODES;
        for (int k = lane; k < KCODES; k += 32) {
            const float4* wp = (const float4*)(W + (size_t)k * DIM);
            float dot = 0.0f;
            #pragma unroll
            for (int gg = 0; gg < 16; ++gg) {
                float4 w4 = __ldg(wp + gg);
                dot += x[gg].x * w4.x; dot += x[gg].y * w4.y;
                dot += x[gg].z * w4.z; dot += x[gg].w * w4.w;
            }
            float tt = sx + s_sw[k];
            float dist = tt - 2.0f * dot;
            if (dist < bd) { bd = dist; bi = k; }        // first-min per lane
        }
        #pragma unroll
        for (int off = 16; off > 0; off >>= 1) {
            float ob = __shfl_xor_sync(0xffffffffu, bd, off);
            int   oi = __shfl_xor_sync(0xffffffffu, bi, off);
            if (ob < bd || (ob == bd && oi < bi)) { bd = ob; bi = oi; }
        }
        if (lane == 0) s_idx[r] = bi;
    }
    __syncthreads();

    // ---- outputs: 2 threads per row ----
    const int row  = tid >> 1;
    const int half = tid & 1;
    const int rowG = rowBase + row;
    const int bidx = s_idx[row];

    if (half == 0) {
        out[2 + (size_t)NROWS * DIM + rowG] = (float)bidx;
        atomicAdd(&g_counts[bidx], 1);
    }

    double lsum = 0.0;
    {
        const float4* qp  = (const float4*)(W + (size_t)bidx * DIM + half * 32);
        const float4* xp2 = (const float4*)(X + (size_t)rowG * DIM + half * 32);
        float* op = out + 1 + (size_t)rowG * DIM + half * 32;  // 4B-aligned only
        #pragma unroll
        for (int gg = 0; gg < 8; ++gg) {
            float4 q4 = __ldg(qp + gg);
            float4 xv = xp2[gg];
            float e;
            e = q4.x - xv.x; op[4*gg + 0] = xv.x + e; lsum += (double)(e * e);
            e = q4.y - xv.y; op[4*gg + 1] = xv.y + e; lsum += (double)(e * e);
            e = q4.z - xv.z; op[4*gg + 2] = xv.z + e; lsum += (double)(e * e);
            e = q4.w - xv.w; op[4*gg + 3] = xv.w + e; lsum += (double)(e * e);
        }
    }

    s_red[tid] = lsum;
    __syncthreads();
    for (int s = TPB / 2; s > 0; s >>= 1) {
        if (tid < s) s_red[tid] += s_red[tid + s];
        __syncthreads();
    }
    if (tid == 0) g_partial[blockIdx.x] = s_red[0];
}

// ---------------------------------------------------------------------------
__global__ void vq_finalize(float* __restrict__ out) {
    __shared__ double sd[512];
    __shared__ float  sf[512];
    const int t = threadIdx.x;  // 512 threads

    double v = 0.0;
    for (int i = t; i < NBLOCKS; i += 512) v += g_partial[i];
    sd[t] = v;

    float c = (float)g_counts[t] / (float)NROWS;
    sf[t] = c * logf(c + 1e-10f);
    __syncthreads();

    for (int s = 256; s > 0; s >>= 1) {
        if (t < s) { sd[t] += sd[t + s]; sf[t] += sf[t + s]; }
        __syncthreads();
    }
    if (t == 0) {
        float m = (float)(sd[0] / ((double)NROWS * (double)DIM));
        out[0] = m + 0.25f * m;
        out[1 + (size_t)NROWS * DIM] = expf(-sf[0]) / (float)KCODES;
    }
}

// ---------------------------------------------------------------------------
extern "C" void kernel_launch(void* const* d_in, const int* in_sizes, int n_in,
                              void* d_out, int out_size) {
    const float* X = (const float*)d_in[0];   // inputs  [N, 64]
    const float* W = (const float*)d_in[1];   // emb_weight [512, 64]
    float* out = (float*)d_out;

    vq_prep<<<KCODES / 64, 64>>>(W);
    vq_main<<<NBLOCKS, TPB>>>(X, W, out);
    vq_finalize<<<1, KCODES>>>(out);
}

// round 12
// speedup vs baseline: 2.6728x; 2.6728x over previous
#include <cuda_runtime.h>
#include <math.h>
#include <stdint.h>

#define KCODES 512
#define DIM 64
#define NROWS 262144
#define TPB 256
#define NBLOCKS (NROWS / TPB)   // 1024
#define CHUNK 128               // codes per smem tile

// Scratch (no allocations allowed)
__device__ float  g_sw[KCODES];
__device__ int    g_counts[KCODES];
__device__ double g_partial[NBLOCKS];

typedef unsigned long long ull;

__device__ __forceinline__ void unpack2(ull v, float& lo, float& hi) {
    asm("mov.b64 {%0, %1}, %2;" : "=f"(lo), "=f"(hi) : "l"(v));
}
__device__ __forceinline__ ull fma2(ull a, ull b, ull c) {
    ull d;
    asm("fma.rn.f32x2 %0, %1, %2, %3;" : "=l"(d) : "l"(a), "l"(b), "l"(c));
    return d;
}
__device__ __forceinline__ ull add2(ull a, ull b) {
    ull d;
    asm("add.rn.f32x2 %0, %1, %2;" : "=l"(d) : "l"(a), "l"(b));
    return d;
}

// ---------------------------------------------------------------------------
// Kernel 1: per-code squared norms + zero histogram
// ---------------------------------------------------------------------------
__global__ void vq_prep(const float* __restrict__ W) {
    int k = blockIdx.x * 64 + threadIdx.x;   // 8 x 64
    const float4* w = (const float4*)(W + (size_t)k * DIM);
    float s = 0.0f;
    #pragma unroll
    for (int g = 0; g < 16; ++g) {
        float4 v = w[g];
        s += v.x * v.x; s += v.y * v.y; s += v.z * v.z; s += v.w * v.w;
    }
    g_sw[k] = s;
    g_counts[k] = 0;
}

// ---------------------------------------------------------------------------
// Kernel 2: FFMA2 dim-pair scoring, argmin, q_st, loss, histogram
// Output layout (float32):
//   out[0] = loss | out[1..1+N*64) = quantized_st | out[1+N*64] = perp
//   out[2+N*64 .. 2+N*64+N) = indices (float)
// ---------------------------------------------------------------------------
__global__ __launch_bounds__(TPB, 2) void vq_main(const float* __restrict__ X,
                                                  const float* __restrict__ W,
                                                  float* __restrict__ out) {
    __shared__ float  s_tile[CHUNK * DIM];   // 32 KB, natural W layout
    __shared__ float  s_sw[KCODES];          // 2 KB
    __shared__ double s_red[TPB];            // 2 KB

    const int tid = threadIdx.x;
    const int row = blockIdx.x * TPB + tid;

    for (int i = tid; i < KCODES; i += TPB) s_sw[i] = g_sw[i];

    // x row as 32 packed dim-pairs {x[2j], x[2j+1]} (memory layout IS pairs)
    ull xx[32];
    {
        const ulonglong2* xp = (const ulonglong2*)(X + (size_t)row * DIM);
        #pragma unroll
        for (int g = 0; g < 16; ++g) {
            ulonglong2 v = xp[g];
            xx[2 * g] = v.x;
            xx[2 * g + 1] = v.y;
        }
    }
    // sx in the exact R2 sequential order
    float sx = 0.0f;
    #pragma unroll
    for (int j = 0; j < 32; ++j) {
        float lo, hi;
        unpack2(xx[j], lo, hi);
        sx += lo * lo;
        sx += hi * hi;
    }

    float best = __int_as_float(0x7f800000);
    int bestIdx = 0;

    for (int c = 0; c < KCODES / CHUNK; ++c) {
        __syncthreads();
        {   // cooperative coalesced tile load (natural layout)
            const float4* wp = (const float4*)(W + (size_t)c * CHUNK * DIM);
            float4* tp = (float4*)s_tile;
            #pragma unroll
            for (int i = tid; i < CHUNK * (DIM / 4); i += TPB) tp[i] = wp[i];
        }
        __syncthreads();

        for (int kk = 0; kk < CHUNK; kk += 2) {
            const ulonglong2* w0 = (const ulonglong2*)(s_tile + kk * DIM);
            const ulonglong2* w1 = w0 + 16;   // next code (+64 floats)
            ull a0 = 0, a1 = 0, a2 = 0, a3 = 0;   // code kk, 4 chains
            ull b0 = 0, b1 = 0, b2 = 0, b3 = 0;   // code kk+1
            #pragma unroll
            for (int g = 0; g < 16; ++g) {        // 16 LDS.128 per code (broadcast)
                ulonglong2 u = w0[g];
                ulonglong2 v = w1[g];
                if ((g & 1) == 0) {
                    a0 = fma2(xx[2 * g], u.x, a0);
                    a1 = fma2(xx[2 * g + 1], u.y, a1);
                    b0 = fma2(xx[2 * g], v.x, b0);
                    b1 = fma2(xx[2 * g + 1], v.y, b1);
                } else {
                    a2 = fma2(xx[2 * g], u.x, a2);
                    a3 = fma2(xx[2 * g + 1], u.y, a3);
                    b2 = fma2(xx[2 * g], v.x, b2);
                    b3 = fma2(xx[2 * g + 1], v.y, b3);
                }
            }
            ull sa = add2(add2(a0, a1), add2(a2, a3));
            ull sb = add2(add2(b0, b1), add2(b2, b3));
            float lo, hi;
            unpack2(sa, lo, hi);
            float dotA = lo + hi;
            unpack2(sb, lo, hi);
            float dotB = lo + hi;

            const int k = c * CHUNK + kk;
            float tA = sx + s_sw[k];
            float tB = sx + s_sw[k + 1];
            float dA = tA - 2.0f * dotA;
            float dB = tB - 2.0f * dotB;
            if (dA < best) { best = dA; bestIdx = k; }       // ascending k,
            if (dB < best) { best = dB; bestIdx = k + 1; }   // strict <
        }
    }

    // gather chosen code, straight-through output + loss contribution.
    // quantized_st region is 4B-aligned only -> scalar stores.
    const float4* qp = (const float4*)(W + (size_t)bestIdx * DIM);
    float* op = out + 1 + (size_t)row * DIM;
    double lsum = 0.0;
    #pragma unroll
    for (int g = 0; g < 16; ++g) {
        float4 q4 = qp[g];
        float x0, x1, x2, x3;
        unpack2(xx[2 * g], x0, x1);
        unpack2(xx[2 * g + 1], x2, x3);
        float e;
        e = q4.x - x0; op[4*g + 0] = x0 + e; lsum += (double)(e * e);
        e = q4.y - x1; op[4*g + 1] = x1 + e; lsum += (double)(e * e);
        e = q4.z - x2; op[4*g + 2] = x2 + e; lsum += (double)(e * e);
        e = q4.w - x3; op[4*g + 3] = x3 + e; lsum += (double)(e * e);
    }

    out[2 + (size_t)NROWS * DIM + row] = (float)bestIdx;
    atomicAdd(&g_counts[bestIdx], 1);

    s_red[tid] = lsum;
    __syncthreads();
    for (int s = TPB / 2; s > 0; s >>= 1) {
        if (tid < s) s_red[tid] += s_red[tid + s];
        __syncthreads();
    }
    if (tid == 0) g_partial[blockIdx.x] = s_red[0];
}

// ---------------------------------------------------------------------------
// Kernel 3: finalize — loss + perplexity scalars
// ---------------------------------------------------------------------------
__global__ void vq_finalize(float* __restrict__ out) {
    __shared__ double sd[512];
    __shared__ float  sf[512];
    const int t = threadIdx.x;  // 512 threads

    double v = 0.0;
    for (int i = t; i < NBLOCKS; i += 512) v += g_partial[i];
    sd[t] = v;

    float c = (float)g_counts[t] / (float)NROWS;
    sf[t] = c * logf(c + 1e-10f);
    __syncthreads();

    for (int s = 256; s > 0; s >>= 1) {
        if (t < s) { sd[t] += sd[t + s]; sf[t] += sf[t + s]; }
        __syncthreads();
    }
    if (t == 0) {
        float m = (float)(sd[0] / ((double)NROWS * (double)DIM));
        out[0] = m + 0.25f * m;
        out[1 + (size_t)NROWS * DIM] = expf(-sf[0]) / (float)KCODES;
    }
}

// ---------------------------------------------------------------------------
extern "C" void kernel_launch(void* const* d_in, const int* in_sizes, int n_in,
                              void* d_out, int out_size) {
    const float* X = (const float*)d_in[0];   // inputs  [N, 64]
    const float* W = (const float*)d_in[1];   // emb_weight [512, 64]
    float* out = (float*)d_out;

    int rows = in_sizes[0] / DIM;             // 262144
    int blocks = rows / TPB;                  // 1024

    vq_prep<<<KCODES / 64, 64>>>(W);
    vq_main<<<blocks, TPB>>>(X, W, out);
    vq_finalize<<<1, KCODES>>>(out);
}

// round 13
// speedup vs baseline: 2.8399x; 1.0625x over previous
#include <cuda_runtime.h>
#include <math.h>
#include <stdint.h>

#define KCODES 512
#define DIM 64
#define NROWS 262144
#define TPB 256
#define ROWSB 128                      // rows per block
#define NBLK (NROWS / ROWSB)           // 2048
#define NKP 32                         // dim-pairs
#define XTP 130                        // xt row stride (ull) — 16B aligned
#define WTP 34                         // wt row stride (ull) — 17x16B skew
#define CCH 32                         // codes per chunk
#define NCH (KCODES / CCH)             // 16

// dynamic smem carve (ull units)
#define XT_OFF 0
#define XT_ULL (NKP * XTP)             // 4160
#define WT_OFF XT_ULL
#define WT_BUF (NKP * WTP)             // 1088
#define MRG_OFF (WT_OFF + 2 * WT_BUF)  // 6336
#define MRG_ULL (ROWSB * 17)           // 2176 float2 slots
#define RED_OFF (MRG_OFF + MRG_ULL)    // 8512
#define DYN_ULL (RED_OFF + TPB)        // 8768
#define DYN_SMEM (DYN_ULL * 8)         // 70144 B

typedef unsigned long long ull;

// Scratch (no allocations allowed)
__device__ float  g_sw[KCODES];
__device__ int    g_counts[KCODES];
__device__ double g_partial[NBLK];
__device__ ull    g_wt[NKP * KCODES];   // pair-transposed W: g_wt[kp*512+c] = {W[c][2kp], W[c][2kp+1]}

__device__ __forceinline__ ull packf2(float lo, float hi) {
    ull r;
    asm("mov.b64 %0, {%1, %2};" : "=l"(r) : "f"(lo), "f"(hi));
    return r;
}
__device__ __forceinline__ void unpack2(ull v, float& lo, float& hi) {
    asm("mov.b64 {%0, %1}, %2;" : "=f"(lo), "=f"(hi) : "l"(v));
}
__device__ __forceinline__ ull fma2(ull a, ull b, ull c) {
    ull d;
    asm("fma.rn.f32x2 %0, %1, %2, %3;" : "=l"(d) : "l"(a), "l"(b), "l"(c));
    return d;
}
__device__ __forceinline__ uint32_t smem_u32(const void* p) {
    uint32_t a;
    asm("{ .reg .u64 t; cvta.to.shared.u64 t, %1; cvt.u32.u64 %0, t; }" : "=r"(a) : "l"(p));
    return a;
}
__device__ __forceinline__ void cpasync8(uint32_t saddr, const void* g) {
    asm volatile("cp.async.ca.shared.global [%0], [%1], 8;" :: "r"(saddr), "l"(g) : "memory");
}

// ---------------------------------------------------------------------------
// Kernel 1: code norms (exact R2 association) + pair-transposed W + hist zero
// ---------------------------------------------------------------------------
__global__ void vq_prep(const float* __restrict__ W) {
    int k = blockIdx.x * 64 + threadIdx.x;   // 8 x 64
    const float4* w = (const float4*)(W + (size_t)k * DIM);
    float s = 0.0f;
    #pragma unroll
    for (int g = 0; g < 16; ++g) {
        float4 v = w[g];
        s += v.x * v.x; s += v.y * v.y; s += v.z * v.z; s += v.w * v.w;
        g_wt[(2 * g) * KCODES + k]     = packf2(v.x, v.y);   // kp = 2g
        g_wt[(2 * g + 1) * KCODES + k] = packf2(v.z, v.w);   // kp = 2g+1
    }
    g_sw[k] = s;
    g_counts[k] = 0;
}

// ---------------------------------------------------------------------------
// Kernel 2: register-tiled fp32x2 GEMM scoring (8 rows x 2 codes / thread)
// Output: out[0]=loss | out[1..1+N*64)=q_st | out[1+N*64]=perp | idx (float)
// ---------------------------------------------------------------------------
__global__ __launch_bounds__(TPB, 2) void vq_main(const float* __restrict__ X,
                                                  const float* __restrict__ W,
                                                  float* __restrict__ out) {
    extern __shared__ __align__(16) ull dynsm[];
    ull*    xt  = dynsm + XT_OFF;                // [32][130]
    ull*    wt  = dynsm + WT_OFF;                // 2 x [32][34]
    float2* mrg = (float2*)(dynsm + MRG_OFF);    // [128][17]
    double* red = (double*)(dynsm + RED_OFF);    // [256]
    __shared__ float s_sw[KCODES];
    __shared__ float s_sx[ROWSB];
    __shared__ int   s_idx[ROWSB];

    const int tid = threadIdx.x;
    const int tr  = tid >> 4;                    // 0..15: row group (8 rows)
    const int tc  = tid & 15;                    // 0..15: code pair group
    const int rowBase = blockIdx.x * ROWSB;

    // ---- fill xt (pair-transposed X tile) + s_sw + s_sx ----
    {
        const float4* xsrc = (const float4*)(X + (size_t)rowBase * DIM);
        for (int i = tid; i < ROWSB * 16; i += TPB) {
            int r = i >> 4, j = i & 15;          // j: float4 index (dims 4j..4j+3)
            float4 v = xsrc[i];
            xt[(2 * j) * XTP + r]     = packf2(v.x, v.y);
            xt[(2 * j + 1) * XTP + r] = packf2(v.z, v.w);
        }
    }
    for (int i = tid; i < KCODES; i += TPB) s_sw[i] = g_sw[i];
    if (tid < ROWSB) {
        // exact sequential sx (R2 association)
        const float4* xp = (const float4*)(X + (size_t)(rowBase + tid) * DIM);
        float sx = 0.0f;
        #pragma unroll
        for (int g = 0; g < 16; ++g) {
            float4 v = xp[g];
            sx += v.x * v.x; sx += v.y * v.y; sx += v.z * v.z; sx += v.w * v.w;
        }
        s_sx[tid] = sx;
    }

    const uint32_t wtb = smem_u32(wt);

    // prefetch chunk 0 into buffer 0
    {
        const ull* src = g_wt;                   // chunk 0: c in [0,32)
        for (int i = tid; i < NKP * CCH; i += TPB) {
            int kp = i >> 5, c = i & 31;
            cpasync8(wtb + (uint32_t)(kp * WTP + c) * 8, src + kp * KCODES + c);
        }
        asm volatile("cp.async.commit_group;" ::: "memory");
    }

    float best[8];
    int   bidx[8];
    #pragma unroll
    for (int r = 0; r < 8; ++r) { best[r] = __int_as_float(0x7f800000); bidx[r] = 0; }

    // ---- chunk loop: 16 chunks of 32 codes ----
    for (int ch = 0; ch < NCH; ++ch) {
        const int buf = ch & 1;
        asm volatile("cp.async.wait_group 0;" ::: "memory");
        __syncthreads();
        if (ch < NCH - 1) {
            const ull* src = g_wt + (ch + 1) * CCH;
            uint32_t dstb = wtb + (uint32_t)((buf ^ 1) * WT_BUF) * 8;
            for (int i = tid; i < NKP * CCH; i += TPB) {
                int kp = i >> 5, c = i & 31;
                cpasync8(dstb + (uint32_t)(kp * WTP + c) * 8, src + kp * KCODES + c);
            }
            asm volatile("cp.async.commit_group;" ::: "memory");
        }

        ull acc[16];
        #pragma unroll
        for (int i = 0; i < 16; ++i) acc[i] = 0;

        const ull* wbuf = wt + buf * WT_BUF;

        #pragma unroll 4
        for (int kp = 0; kp < NKP; ++kp) {
            const ulonglong2* xp = (const ulonglong2*)(xt + kp * XTP + tr * 8);
            ulonglong2 x01 = xp[0], x23 = xp[1], x45 = xp[2], x67 = xp[3];
            ulonglong2 wv = *(const ulonglong2*)(wbuf + kp * WTP + 2 * tc);
            acc[0]  = fma2(x01.x, wv.x, acc[0]);  acc[1]  = fma2(x01.x, wv.y, acc[1]);
            acc[2]  = fma2(x01.y, wv.x, acc[2]);  acc[3]  = fma2(x01.y, wv.y, acc[3]);
            acc[4]  = fma2(x23.x, wv.x, acc[4]);  acc[5]  = fma2(x23.x, wv.y, acc[5]);
            acc[6]  = fma2(x23.y, wv.x, acc[6]);  acc[7]  = fma2(x23.y, wv.y, acc[7]);
            acc[8]  = fma2(x45.x, wv.x, acc[8]);  acc[9]  = fma2(x45.x, wv.y, acc[9]);
            acc[10] = fma2(x45.y, wv.x, acc[10]); acc[11] = fma2(x45.y, wv.y, acc[11]);
            acc[12] = fma2(x67.x, wv.x, acc[12]); acc[13] = fma2(x67.x, wv.y, acc[13]);
            acc[14] = fma2(x67.y, wv.x, acc[14]); acc[15] = fma2(x67.y, wv.y, acc[15]);
        }

        // chunk epilogue: dist + running argmin (ascending k in-thread)
        #pragma unroll
        for (int r = 0; r < 8; ++r) {
            const float sxr = s_sx[tr * 8 + r];
            #pragma unroll
            for (int c = 0; c < 2; ++c) {
                float lo, hi;
                unpack2(acc[r * 2 + c], lo, hi);
                float dot = lo + hi;
                const int k = ch * CCH + 2 * tc + c;
                float d = (sxr + s_sw[k]) - 2.0f * dot;
                if (d < best[r]) { best[r] = d; bidx[r] = k; }
            }
        }
    }

    // ---- cross-thread merge: lexicographic (dist, k) = exact first-min ----
    #pragma unroll
    for (int r = 0; r < 8; ++r)
        mrg[(tr * 8 + r) * 17 + tc] = make_float2(best[r], __int_as_float(bidx[r]));
    __syncthreads();

    if (tid < ROWSB) {
        float bd = __int_as_float(0x7f800000);
        int bi = KCODES;
        #pragma unroll
        for (int t = 0; t < 16; ++t) {
            float2 e = mrg[tid * 17 + t];
            int ei = __float_as_int(e.y);
            if (e.x < bd || (e.x == bd && ei < bi)) { bd = e.x; bi = ei; }
        }
        s_idx[tid] = bi;
        out[2 + (size_t)NROWS * DIM + rowBase + tid] = (float)bi;
        atomicAdd(&g_counts[bi], 1);
    }
    __syncthreads();

    // ---- q_st + loss: 2 threads per row (4B-aligned region -> scalar STG) ----
    const int row  = tid >> 1;
    const int half = tid & 1;
    const int rowG = rowBase + row;
    const int kb   = s_idx[row];

    double lsum = 0.0;
    {
        const float4* qp  = (const float4*)(W + (size_t)kb * DIM + half * 32);
        const float4* xp2 = (const float4*)(X + (size_t)rowG * DIM + half * 32);
        float* op = out + 1 + (size_t)rowG * DIM + half * 32;
        #pragma unroll
        for (int g = 0; g < 8; ++g) {
            float4 q4 = __ldg(qp + g);
            float4 xv = xp2[g];
            float e;
            e = q4.x - xv.x; op[4*g + 0] = xv.x + e; lsum += (double)(e * e);
            e = q4.y - xv.y; op[4*g + 1] = xv.y + e; lsum += (double)(e * e);
            e = q4.z - xv.z; op[4*g + 2] = xv.z + e; lsum += (double)(e * e);
            e = q4.w - xv.w; op[4*g + 3] = xv.w + e; lsum += (double)(e * e);
        }
    }

    red[tid] = lsum;
    __syncthreads();
    for (int s = TPB / 2; s > 0; s >>= 1) {
        if (tid < s) red[tid] += red[tid + s];
        __syncthreads();
    }
    if (tid == 0) g_partial[blockIdx.x] = red[0];
}

// ---------------------------------------------------------------------------
// Kernel 3: finalize — loss + perplexity scalars
// ---------------------------------------------------------------------------
__global__ void vq_finalize(float* __restrict__ out) {
    __shared__ double sd[512];
    __shared__ float  sf[512];
    const int t = threadIdx.x;  // 512 threads

    double v = 0.0;
    for (int i = t; i < NBLK; i += 512) v += g_partial[i];
    sd[t] = v;

    float c = (float)g_counts[t] / (float)NROWS;
    sf[t] = c * logf(c + 1e-10f);
    __syncthreads();

    for (int s = 256; s > 0; s >>= 1) {
        if (t < s) { sd[t] += sd[t + s]; sf[t] += sf[t + s]; }
        __syncthreads();
    }
    if (t == 0) {
        float m = (float)(sd[0] / ((double)NROWS * (double)DIM));
        out[0] = m + 0.25f * m;
        out[1 + (size_t)NROWS * DIM] = expf(-sf[0]) / (float)KCODES;
    }
}

// ---------------------------------------------------------------------------
extern "C" void kernel_launch(void* const* d_in, const int* in_sizes, int n_in,
                              void* d_out, int out_size) {
    const float* X = (const float*)d_in[0];   // inputs  [N, 64]
    const float* W = (const float*)d_in[1];   // emb_weight [512, 64]
    float* out = (float*)d_out;

    cudaFuncSetAttribute((const void*)vq_main,
                         cudaFuncAttributeMaxDynamicSharedMemorySize, DYN_SMEM);

    vq_prep<<<KCODES / 64, 64>>>(W);
    vq_main<<<NBLK, TPB, DYN_SMEM>>>(X, W, out);
    vq_finalize<<<1, KCODES>>>(out);
}